// round 7
// baseline (speedup 1.0000x reference)
#include <cuda_runtime.h>
#include <cstdint>

#define NA    768
#define NM1   767
#define NE    (768*767)      // 589056
#define DIM   64
#define NCONV 3
#define GAPF  0.10204081632653061f   // 5/49
#define NJT   48                      // j-tiles per i (768/16)
#define TSTRIDE 68

// ---------------- device scratch ----------------
__device__ float g_h    [NA * DIM];
__device__ float g_nw   [NA * DIM];
__device__ float g_agg  [NA * DIM];
__device__ float g_nwsum[NCONV * DIM];
__device__ float g_ha   [NA];
// rbf in A-fragment order: [i][jt][kk][lane] (float4 each) = 768*48*7*32 float4
__device__ float4 g_rbfF[NA * NJT * 7 * 32];

// ---------------- tf32 helpers ----------------
__device__ __forceinline__ uint32_t f2tf(float x) {
    uint32_t u; asm("cvt.rna.tf32.f32 %0, %1;" : "=r"(u) : "f"(x)); return u;
}
__device__ __forceinline__ float f2tf_f(float x) { return __uint_as_float(f2tf(x)); }

// mma.sync m16n8k8 tf32: D(16x8,f32) += A(16x8,tf32) * B(8x8,tf32)
__device__ __forceinline__ void mma8(float* d, uint32_t a0, uint32_t a1, uint32_t a2, uint32_t a3,
                                     uint32_t b0, uint32_t b1) {
    asm volatile("mma.sync.aligned.m16n8k8.row.col.f32.tf32.tf32.f32 "
                 "{%0,%1,%2,%3},{%4,%5,%6,%7},{%8,%9},{%0,%1,%2,%3};"
                 : "+f"(d[0]), "+f"(d[1]), "+f"(d[2]), "+f"(d[3])
                 : "r"(a0), "r"(a1), "r"(a2), "r"(a3), "r"(b0), "r"(b1));
}

__device__ __forceinline__ float rbff(float d, int k) {
    float mu = (float)k * GAPF;
    float v = d - mu;
    return __expf(-9.8f * v * v);
}
// softplus_bt(x, beta=0.5, thr=14)
__device__ __forceinline__ float sp_half(float x) {
    float t = 0.5f * x;
    if (t > 14.0f) return x;
    return 2.0f * (fmaxf(t, 0.0f) + __logf(1.0f + __expf(-fabsf(t))));
}

// ---------------- small per-atom kernels ----------------
__global__ void k_init_h(const int* __restrict__ at, const float* __restrict__ emb) {
    int idx = blockIdx.x * blockDim.x + threadIdx.x;
    if (idx < NA * DIM) g_h[idx] = emb[at[idx >> 6] * DIM + (idx & 63)];
    if (idx < NCONV * DIM) g_nwsum[idx] = 0.0f;
}

// rbf writer: block = (i,jt) tile, 224 threads = 7 kk * 32 lanes
__global__ void __launch_bounds__(224)
k_rbfF(const float* __restrict__ dist) {
    __shared__ float sd[16];
    int b = blockIdx.x;              // i*NJT + jt
    int i = b / NJT, jt = b - i * NJT;
    int tid = threadIdx.x;
    if (tid < 16) {
        int j = jt * 16 + tid;
        sd[tid] = (j == i) ? 0.0f : dist[i * NM1 + j - (j > i ? 1 : 0)];
    }
    __syncthreads();
    int kk = tid >> 5, l = tid & 31, g = l >> 2, tq = l & 3;
    int k0 = kk * 8 + tq;
    float d0 = sd[g], d1 = sd[g + 8];
    float4 v;
    v.x = f2tf_f(rbff(d0, k0));
    v.y = f2tf_f(rbff(d1, k0));
    v.z = f2tf_f(rbff(d0, k0 + 4));
    v.w = f2tf_f(rbff(d1, k0 + 4));
    g_rbfF[(b * 7 + kk) * 32 + l] = v;
}

__global__ void k_nw(const float* __restrict__ w1l, float* __restrict__ nws) {
    __shared__ float hrow[DIM];
    int i = blockIdx.x, c = threadIdx.x;
    hrow[c] = g_h[i * DIM + c];
    __syncthreads();
    float s = 0.0f;
#pragma unroll
    for (int k = 0; k < DIM; k++) s += hrow[k] * w1l[k * DIM + c];
    g_nw[i * DIM + c]  = s;
    g_agg[i * DIM + c] = 0.0f;
    atomicAdd(&nws[c], s);
}

__global__ void k_update(const float* __restrict__ qw1l, const float* __restrict__ qb1l,
                         const float* __restrict__ qw2l, const float* __restrict__ qb2l,
                         const float* __restrict__ pb2l, const float* __restrict__ nws) {
    __shared__ float arow[DIM];
    __shared__ float trow[DIM];
    int i = blockIdx.x, c = threadIdx.x;
    arow[c] = g_agg[i * DIM + c] + pb2l[c] * (nws[c] - g_nw[i * DIM + c]);
    __syncthreads();
    float s = qb1l[c];
#pragma unroll
    for (int k = 0; k < DIM; k++) s += arow[k] * qw1l[k * DIM + c];
    trow[c] = sp_half(s);
    __syncthreads();
    float s2 = qb2l[c];
#pragma unroll
    for (int k = 0; k < DIM; k++) s2 += trow[k] * qw2l[k * DIM + c];
    g_h[i * DIM + c] += s2;
}

__global__ void k_atom(const float* __restrict__ au_w1, const float* __restrict__ au_b1,
                       const float* __restrict__ au_w2, const float* __restrict__ au_b2) {
    __shared__ float hrow[DIM];
    __shared__ float red[DIM];
    int i = blockIdx.x, c = threadIdx.x;
    hrow[c] = g_h[i * DIM + c];
    __syncthreads();
    float s = au_b1[c];
#pragma unroll
    for (int k = 0; k < DIM; k++) s += hrow[k] * au_w1[k * DIM + c];
    float sp = (s > 20.0f) ? s : (fmaxf(s, 0.0f) + log1pf(__expf(-fabsf(s))));
    sp -= 0.69314718055994530942f;
    red[c] = sp * au_w2[c];
    __syncthreads();
    if (c < 32) {
        float v = red[c] + red[c + 32];
#pragma unroll
        for (int off = 16; off; off >>= 1) v += __shfl_down_sync(0xffffffffu, v, off);
        if (c == 0) g_ha[i] = v + au_b2[0];
    }
}

// ======================= fused conv via tensor cores =======================
// Block: 256 threads = 8 warps. Warp w owns 16 dst rows (tile jt = bx*8+w).
// Loop over 16 src atoms i (chunk = blockIdx.y).
// GEMM1: u = rbfF @ pw1 + pb1 ; softplus (diag row zeroed) -> t (tf32, smem)
// GEMM2: u2 = t @ pw2 (unscaled) ; acc += nw[i]_col * u2
__global__ void __launch_bounds__(256, 2)
k_conv(const float* __restrict__ pw1l, const float* __restrict__ pb1l,
       const float* __restrict__ pw2l) {
    extern __shared__ float sm[];
    float* s_bf1 = sm;            // 7*4*32*4 = 3584 (frag order, tf32, k>=50 zero)
    float* s_bf2 = sm + 3584;     // 8*4*32*4 = 4096 (frag order, tf32)
    float* s_pb1 = sm + 7680;     // 64
    float* s_nw  = sm + 7744;     // 16*64
    float* s_tb  = sm + 8768;     // 8 * 16 * TSTRIDE

    int tid  = threadIdx.x;
    int warp = tid >> 5, lane = tid & 31;
    int g = lane >> 2, tq = lane & 3;
    int i0 = blockIdx.y * 16;

    for (int idx = tid; idx < 3584; idx += 256) {
        int kk = idx >> 9, c4 = (idx >> 7) & 3, l = (idx >> 2) & 31, jj = idx & 3;
        int k = kk * 8 + (l & 3) + 4 * (jj & 1);
        int n = (c4 * 2 + (jj >> 1)) * 8 + (l >> 2);
        s_bf1[idx] = (k < 50) ? f2tf_f(pw1l[k * 64 + n]) : 0.0f;
    }
    for (int idx = tid; idx < 4096; idx += 256) {
        int kk = idx >> 9, c4 = (idx >> 7) & 3, l = (idx >> 2) & 31, jj = idx & 3;
        int k = kk * 8 + (l & 3) + 4 * (jj & 1);
        int n = (c4 * 2 + (jj >> 1)) * 8 + (l >> 2);
        s_bf2[idx] = f2tf_f(pw2l[k * 64 + n]);
    }
    if (tid < 64) s_pb1[tid] = pb1l[tid];
    for (int idx = tid; idx < 16 * 64; idx += 256) s_nw[idx] = g_nw[i0 * 64 + idx];
    __syncthreads();

    int jt = blockIdx.x * 8 + warp;
    int j0 = jt * 16 + g, j1 = j0 + 8;
    float* st = s_tb + warp * (16 * TSTRIDE);

    float acc[8][4];
#pragma unroll
    for (int nt = 0; nt < 8; nt++)
#pragma unroll
        for (int q = 0; q < 4; q++) acc[nt][q] = 0.0f;

#pragma unroll 1
    for (int ii = 0; ii < 16; ii++) {
        int i = i0 + ii;
        const float4* rA = &g_rbfF[((i * NJT + jt) * 7) * 32 + lane];

        // ---- GEMM1: u = rbfF @ pw1 + pb1 ----
        float u[8][4];
#pragma unroll
        for (int nt = 0; nt < 8; nt++) {
            float2 pb = *(const float2*)&s_pb1[nt * 8 + 2 * tq];
            u[nt][0] = pb.x; u[nt][1] = pb.y; u[nt][2] = pb.x; u[nt][3] = pb.y;
        }
#pragma unroll
        for (int kk = 0; kk < 7; kk++) {
            float4 a = rA[kk * 32];
            uint32_t a0 = __float_as_uint(a.x), a1 = __float_as_uint(a.y);
            uint32_t a2 = __float_as_uint(a.z), a3 = __float_as_uint(a.w);
#pragma unroll
            for (int c4 = 0; c4 < 4; c4++) {
                float4 b = *(const float4*)&s_bf1[kk * 512 + c4 * 128 + lane * 4];
                mma8(u[2 * c4],     a0, a1, a2, a3, __float_as_uint(b.x), __float_as_uint(b.y));
                mma8(u[2 * c4 + 1], a0, a1, a2, a3, __float_as_uint(b.z), __float_as_uint(b.w));
            }
        }

        // ---- softplus, zero diag rows, stage t (pre-converted tf32) ----
        bool z0 = (j0 == i), z1 = (j1 == i);
        __syncwarp();
#pragma unroll
        for (int nt = 0; nt < 8; nt++) {
            int col = nt * 8 + 2 * tq;
            float2 r0 = make_float2(z0 ? 0.0f : f2tf_f(sp_half(u[nt][0])),
                                    z0 ? 0.0f : f2tf_f(sp_half(u[nt][1])));
            float2 r1 = make_float2(z1 ? 0.0f : f2tf_f(sp_half(u[nt][2])),
                                    z1 ? 0.0f : f2tf_f(sp_half(u[nt][3])));
            *(float2*)&st[g * TSTRIDE + col]       = r0;
            *(float2*)&st[(g + 8) * TSTRIDE + col] = r1;
        }
        __syncwarp();

        // ---- GEMM2: u2 = t @ pw2 (unscaled) ----
#pragma unroll
        for (int nt = 0; nt < 8; nt++)
#pragma unroll
            for (int q = 0; q < 4; q++) u[nt][q] = 0.0f;
#pragma unroll
        for (int kk = 0; kk < 8; kk++) {
            int k0 = kk * 8 + tq;
            uint32_t a0 = __float_as_uint(st[g * TSTRIDE + k0]);
            uint32_t a1 = __float_as_uint(st[(g + 8) * TSTRIDE + k0]);
            uint32_t a2 = __float_as_uint(st[g * TSTRIDE + k0 + 4]);
            uint32_t a3 = __float_as_uint(st[(g + 8) * TSTRIDE + k0 + 4]);
#pragma unroll
            for (int c4 = 0; c4 < 4; c4++) {
                float4 b = *(const float4*)&s_bf2[kk * 512 + c4 * 128 + lane * 4];
                mma8(u[2 * c4],     a0, a1, a2, a3, __float_as_uint(b.x), __float_as_uint(b.y));
                mma8(u[2 * c4 + 1], a0, a1, a2, a3, __float_as_uint(b.z), __float_as_uint(b.w));
            }
        }

        // ---- acc += nw[i]_col * u2 (fp32 scale, was per-element B rescale) ----
#pragma unroll
        for (int nt = 0; nt < 8; nt++) {
            float2 w = *(const float2*)&s_nw[ii * 64 + nt * 8 + 2 * tq];
            acc[nt][0] += w.x * u[nt][0];
            acc[nt][1] += w.y * u[nt][1];
            acc[nt][2] += w.x * u[nt][2];
            acc[nt][3] += w.y * u[nt][3];
        }
    }

#pragma unroll
    for (int nt = 0; nt < 8; nt++) {
        int col = nt * 8 + 2 * tq;
        atomicAdd(&g_agg[j0 * 64 + col],     acc[nt][0]);
        atomicAdd(&g_agg[j0 * 64 + col + 1], acc[nt][1]);
        atomicAdd(&g_agg[j1 * 64 + col],     acc[nt][2]);
        atomicAdd(&g_agg[j1 * 64 + col + 1], acc[nt][3]);
    }
}

// ======================= readout via tensor cores, (i,j) tiling ==============
__global__ void __launch_bounds__(256, 2)
k_readout(const float* __restrict__ ro_w1, const float* __restrict__ ro_b1,
          const float* __restrict__ ro_w2, const float* __restrict__ ro_b2,
          float* __restrict__ out) {
    __shared__ __align__(16) float s_wg[3584];     // rbf-part weights, frag order
    __shared__ __align__(16) float s_wa[64];       // row 0 (ha_src)
    __shared__ __align__(16) float s_wb[64];       // row 1 (ha_dst)
    __shared__ __align__(16) float s_b1[64];
    __shared__ __align__(16) float s_w2[128];      // [64][2]
    __shared__ float s_b2[2];

    int tid  = threadIdx.x;
    int warp = tid >> 5, lane = tid & 31;
    int g = lane >> 2, tq = lane & 3;

    for (int idx = tid; idx < 3584; idx += 256) {
        int kk = idx >> 9, c4 = (idx >> 7) & 3, l = (idx >> 2) & 31, jj = idx & 3;
        int k = kk * 8 + (l & 3) + 4 * (jj & 1);
        int n = (c4 * 2 + (jj >> 1)) * 8 + (l >> 2);
        s_wg[idx] = (k < 50) ? f2tf_f(ro_w1[(2 + k) * 64 + n]) : 0.0f;
    }
    if (tid < 64)  { s_wa[tid] = ro_w1[tid]; s_wb[tid] = ro_w1[64 + tid]; s_b1[tid] = ro_b1[tid]; }
    if (tid < 128) s_w2[tid] = ro_w2[tid];
    if (tid < 2)   s_b2[tid] = ro_b2[tid];
    __syncthreads();

    int t  = blockIdx.x * 8 + warp;                // (i, jt) tile
    int i  = t / NJT, jt = t - i * NJT;
    int j0 = jt * 16 + g, j1 = j0 + 8;
    float hi = g_ha[i], hj0 = g_ha[j0], hj1 = g_ha[j1];

    float f[8][4];
#pragma unroll
    for (int nt = 0; nt < 8; nt++) {
        int col = nt * 8 + 2 * tq;
        float2 b  = *(const float2*)&s_b1[col];
        float2 wa = *(const float2*)&s_wa[col];
        float2 wb = *(const float2*)&s_wb[col];
        f[nt][0] = b.x + hi * wa.x + hj0 * wb.x;
        f[nt][1] = b.y + hi * wa.y + hj0 * wb.y;
        f[nt][2] = b.x + hi * wa.x + hj1 * wb.x;
        f[nt][3] = b.y + hi * wa.y + hj1 * wb.y;
    }
    const float4* rA = &g_rbfF[((i * NJT + jt) * 7) * 32 + lane];
#pragma unroll
    for (int kk = 0; kk < 7; kk++) {
        float4 a = rA[kk * 32];
        uint32_t a0 = __float_as_uint(a.x), a1 = __float_as_uint(a.y);
        uint32_t a2 = __float_as_uint(a.z), a3 = __float_as_uint(a.w);
#pragma unroll
        for (int c4 = 0; c4 < 4; c4++) {
            float4 b = *(const float4*)&s_wg[kk * 512 + c4 * 128 + lane * 4];
            mma8(f[2 * c4],     a0, a1, a2, a3, __float_as_uint(b.x), __float_as_uint(b.y));
            mma8(f[2 * c4 + 1], a0, a1, a2, a3, __float_as_uint(b.z), __float_as_uint(b.w));
        }
    }

    // epilogue: relu -> 64x2 head -> 4-lane reduce -> softmax
    float l00 = 0.0f, l01 = 0.0f, l10 = 0.0f, l11 = 0.0f;
#pragma unroll
    for (int nt = 0; nt < 8; nt++) {
        int col = nt * 8 + 2 * tq;
        float4 w = *(const float4*)&s_w2[col * 2];
        float v0 = fmaxf(f[nt][0], 0.0f), v1 = fmaxf(f[nt][1], 0.0f);
        float v2 = fmaxf(f[nt][2], 0.0f), v3 = fmaxf(f[nt][3], 0.0f);
        l00 += v0 * w.x + v1 * w.z;  l01 += v0 * w.y + v1 * w.w;
        l10 += v2 * w.x + v3 * w.z;  l11 += v2 * w.y + v3 * w.w;
    }
#pragma unroll
    for (int off = 1; off <= 2; off <<= 1) {
        l00 += __shfl_xor_sync(0xffffffffu, l00, off);
        l01 += __shfl_xor_sync(0xffffffffu, l01, off);
        l10 += __shfl_xor_sync(0xffffffffu, l10, off);
        l11 += __shfl_xor_sync(0xffffffffu, l11, off);
    }
    if (tq == 0) {
        if (j0 != i) {
            int e0 = i * NM1 + j0 - (j0 > i ? 1 : 0);
            float a = l00 + s_b2[0], b = l01 + s_b2[1];
            float m = fmaxf(a, b);
            float pa = __expf(a - m), pb = __expf(b - m);
            float inv = 1.0f / (pa + pb);
            *(float2*)&out[2 * e0] = make_float2(pa * inv, pb * inv);
        }
        if (j1 != i) {
            int e1 = i * NM1 + j1 - (j1 > i ? 1 : 0);
            float a = l10 + s_b2[0], b = l11 + s_b2[1];
            float m = fmaxf(a, b);
            float pa = __expf(a - m), pb = __expf(b - m);
            float inv = 1.0f / (pa + pb);
            *(float2*)&out[2 * e1] = make_float2(pa * inv, pb * inv);
        }
    }
}

// ---------------- launch ------------------------------------------------------
extern "C" void kernel_launch(void* const* d_in, const int* in_sizes, int n_in,
                              void* d_out, int out_size) {
    const int*   at    = (const int*)  d_in[0];
    const float* dist  = (const float*)d_in[1];
    // d_in[2]=src, d_in[3]=dst implied by complete-graph closed form
    const float* emb   = (const float*)d_in[4];
    const float* w1    = (const float*)d_in[5];
    const float* pw1   = (const float*)d_in[6];
    const float* pb1   = (const float*)d_in[7];
    const float* pw2   = (const float*)d_in[8];
    const float* pb2   = (const float*)d_in[9];
    const float* qw1   = (const float*)d_in[10];
    const float* qb1   = (const float*)d_in[11];
    const float* qw2   = (const float*)d_in[12];
    const float* qb2   = (const float*)d_in[13];
    const float* au_w1 = (const float*)d_in[14];
    const float* au_b1 = (const float*)d_in[15];
    const float* au_w2 = (const float*)d_in[16];
    const float* au_b2 = (const float*)d_in[17];
    const float* ro_w1 = (const float*)d_in[18];
    const float* ro_b1 = (const float*)d_in[19];
    const float* ro_w2 = (const float*)d_in[20];
    const float* ro_b2 = (const float*)d_in[21];
    float* out = (float*)d_out;

    float* nwsum_base;
    cudaGetSymbolAddress((void**)&nwsum_base, g_nwsum);

    const int conv_smem = (3584 + 4096 + 64 + 1024 + 8 * 16 * TSTRIDE) * (int)sizeof(float);
    cudaFuncSetAttribute(k_conv, cudaFuncAttributeMaxDynamicSharedMemorySize, conv_smem);

    k_init_h<<<(NA * DIM + 255) / 256, 256>>>(at, emb);
    k_rbfF<<<NA * NJT, 224>>>(dist);

    for (int l = 0; l < NCONV; l++) {
        k_nw<<<NA, DIM>>>(w1 + l * DIM * DIM, nwsum_base + l * DIM);
        dim3 grid(NA / 128, 48);              // jt-blocks x i-chunks
        k_conv<<<grid, 256, conv_smem>>>(pw1 + l * 50 * DIM, pb1 + l * DIM,
                                         pw2 + l * DIM * DIM);
        k_update<<<NA, DIM>>>(qw1 + l * DIM * DIM, qb1 + l * DIM,
                              qw2 + l * DIM * DIM, qb2 + l * DIM,
                              pb2 + l * DIM, nwsum_base + l * DIM);
    }
    k_atom<<<NA, DIM>>>(au_w1, au_b1, au_w2, au_b2);
    k_readout<<<NA * NJT / 8, 256>>>(ro_w1, ro_b1, ro_w2, ro_b2, out);
}

// round 9
// speedup vs baseline: 1.4902x; 1.4902x over previous
#include <cuda_runtime.h>
#include <cstdint>

#define NA    768
#define NM1   767
#define NE    (768*767)
#define DIM   64
#define NCONV 3
#define NJT   48                      // j-tiles of 16 (768/16)
#define TSTRIDE 68

#define CSQ  3.7601079f               // sqrt(9.8 * log2(e))
#define GC   0.38368448f              // gap * CSQ, gap = 5/49
#define L2E  1.4426950f
#define LN2  0.69314718f

// ---------------- device scratch ----------------
__device__ float g_h    [NA * DIM];
__device__ float g_nw   [NA * DIM];
__device__ float g_agg  [NA * DIM];
__device__ float g_nwsum[NCONV * DIM];
__device__ float g_ha   [NA];

// ---------------- helpers ----------------
__device__ __forceinline__ uint32_t f2tf(float x) {
    uint32_t u; asm("cvt.rna.tf32.f32 %0, %1;" : "=r"(u) : "f"(x)); return u;
}
__device__ __forceinline__ float f2tf_f(float x) { return __uint_as_float(f2tf(x)); }
__device__ __forceinline__ float ex2f(float x) {
    float y; asm("ex2.approx.f32 %0, %1;" : "=f"(y) : "f"(x)); return y;
}
__device__ __forceinline__ float lg2f(float x) {
    float y; asm("lg2.approx.f32 %0, %1;" : "=f"(y) : "f"(x)); return y;
}

// mma.sync m16n8k8 tf32 (raw fp32 operands: HW truncates mantissa)
__device__ __forceinline__ void mma8(float* d, uint32_t a0, uint32_t a1, uint32_t a2, uint32_t a3,
                                     uint32_t b0, uint32_t b1) {
    asm volatile("mma.sync.aligned.m16n8k8.row.col.f32.tf32.tf32.f32 "
                 "{%0,%1,%2,%3},{%4,%5,%6,%7},{%8,%9},{%0,%1,%2,%3};"
                 : "+f"(d[0]), "+f"(d[1]), "+f"(d[2]), "+f"(d[3])
                 : "r"(a0), "r"(a1), "r"(a2), "r"(a3), "r"(b0), "r"(b1));
}

// softplus_bt(x, beta=0.5, thr=14); branch-free, naturally linear for large x
__device__ __forceinline__ float sp_half(float x) {
    float t = 0.5f * x;
    float e = ex2f(-L2E * fabsf(t));
    float l = lg2f(1.0f + e);
    float m = fmaxf(t, 0.0f);
    return 2.0f * fmaf(LN2, l, m);
}

// rbf value bits at parameter t = d*CSQ - k*GC : exp(-9.8 (d-k g)^2) = 2^(-t^2)
__device__ __forceinline__ uint32_t rbf_bits(float t) {
    return __float_as_uint(ex2f(-t * t));
}

// ---------------- small per-atom kernels ----------------
__global__ void k_init_h(const int* __restrict__ at, const float* __restrict__ emb) {
    int idx = blockIdx.x * blockDim.x + threadIdx.x;
    if (idx < NA * DIM) g_h[idx] = emb[at[idx >> 6] * DIM + (idx & 63)];
    if (idx < NCONV * DIM) g_nwsum[idx] = 0.0f;
}

__global__ void k_nw(const float* __restrict__ w1l, float* __restrict__ nws) {
    __shared__ float hrow[DIM];
    int i = blockIdx.x, c = threadIdx.x;
    hrow[c] = g_h[i * DIM + c];
    __syncthreads();
    float s = 0.0f;
#pragma unroll
    for (int k = 0; k < DIM; k++) s += hrow[k] * w1l[k * DIM + c];
    g_nw[i * DIM + c]  = s;
    g_agg[i * DIM + c] = 0.0f;
    atomicAdd(&nws[c], s);
}

// update for layer l; optionally fused nw for layer l+1 (do_nw)
__global__ void k_update(const float* __restrict__ qw1l, const float* __restrict__ qb1l,
                         const float* __restrict__ qw2l, const float* __restrict__ qb2l,
                         const float* __restrict__ pb2l, const float* __restrict__ nws,
                         const float* __restrict__ w1next, float* __restrict__ nwsnext,
                         int do_nw) {
    __shared__ float arow[DIM];
    __shared__ float trow[DIM];
    __shared__ float hrow[DIM];
    int i = blockIdx.x, c = threadIdx.x;
    arow[c] = g_agg[i * DIM + c] + pb2l[c] * (nws[c] - g_nw[i * DIM + c]);
    g_agg[i * DIM + c] = 0.0f;        // ready for next layer
    __syncthreads();
    float s = qb1l[c];
#pragma unroll
    for (int k = 0; k < DIM; k++) s += arow[k] * qw1l[k * DIM + c];
    trow[c] = sp_half(s);
    __syncthreads();
    float s2 = qb2l[c];
#pragma unroll
    for (int k = 0; k < DIM; k++) s2 += trow[k] * qw2l[k * DIM + c];
    float hn = g_h[i * DIM + c] + s2;
    g_h[i * DIM + c] = hn;
    if (do_nw) {
        hrow[c] = hn;
        __syncthreads();
        float s3 = 0.0f;
#pragma unroll
        for (int k = 0; k < DIM; k++) s3 += hrow[k] * w1next[k * DIM + c];
        g_nw[i * DIM + c] = s3;
        atomicAdd(&nwsnext[c], s3);
    }
}

__global__ void k_atom(const float* __restrict__ au_w1, const float* __restrict__ au_b1,
                       const float* __restrict__ au_w2, const float* __restrict__ au_b2) {
    __shared__ float hrow[DIM];
    __shared__ float red[DIM];
    int i = blockIdx.x, c = threadIdx.x;
    hrow[c] = g_h[i * DIM + c];
    __syncthreads();
    float s = au_b1[c];
#pragma unroll
    for (int k = 0; k < DIM; k++) s += hrow[k] * au_w1[k * DIM + c];
    float sp = (s > 20.0f) ? s : (fmaxf(s, 0.0f) + log1pf(__expf(-fabsf(s))));
    sp -= 0.69314718055994530942f;
    red[c] = sp * au_w2[c];
    __syncthreads();
    if (c < 32) {
        float v = red[c] + red[c + 32];
#pragma unroll
        for (int off = 16; off; off >>= 1) v += __shfl_down_sync(0xffffffffu, v, off);
        if (c == 0) g_ha[i] = v + au_b2[0];
    }
}

// ======================= fused conv via tensor cores =======================
// Block: 256 threads = 8 warps. Warp w owns 16 dst rows (tile jt = bx*8+w).
// i-chunk of 16 = blockIdx.y. rbf recomputed in-register from dist (smem-staged).
// GEMM1: u = rbf @ pw1 + pb1 ; softplus (diag zeroed) -> t staged (raw fp32)
// GEMM2: u2 = t @ pw2 ; acc += nw[i]_col * u2  (fp32 scale epilogue)
__global__ void __launch_bounds__(256, 2)
k_conv(const float* __restrict__ dist,
       const float* __restrict__ pw1l, const float* __restrict__ pb1l,
       const float* __restrict__ pw2l) {
    extern __shared__ float sm[];
    float* s_bf1 = sm;            // 3584: pw1 frag order, tf32-rna, k>=50 zero
    float* s_bf2 = sm + 3584;     // 4096: pw2 frag order, tf32-rna
    float* s_pb1 = sm + 7680;     // 64
    float* s_nw  = sm + 7744;     // 1024: nw rows for this i-chunk
    float* s_d   = sm + 8768;     // 2048: dist tile [16 i][128 j], diag=0
    float* s_tb  = sm + 10816;    // 8704: 8 warps * 16 * TSTRIDE

    int tid  = threadIdx.x;
    int warp = tid >> 5, lane = tid & 31;
    int g = lane >> 2, tq = lane & 3;
    int i0 = blockIdx.y * 16;
    int jbase = blockIdx.x * 128;

    for (int idx = tid; idx < 3584; idx += 256) {
        int kk = idx >> 9, c4 = (idx >> 7) & 3, l = (idx >> 2) & 31, jj = idx & 3;
        int k = kk * 8 + (l & 3) + 4 * (jj & 1);
        int n = (c4 * 2 + (jj >> 1)) * 8 + (l >> 2);
        s_bf1[idx] = (k < 50) ? f2tf_f(pw1l[k * 64 + n]) : 0.0f;
    }
    for (int idx = tid; idx < 4096; idx += 256) {
        int kk = idx >> 9, c4 = (idx >> 7) & 3, l = (idx >> 2) & 31, jj = idx & 3;
        int k = kk * 8 + (l & 3) + 4 * (jj & 1);
        int n = (c4 * 2 + (jj >> 1)) * 8 + (l >> 2);
        s_bf2[idx] = f2tf_f(pw2l[k * 64 + n]);
    }
    if (tid < 64) s_pb1[tid] = pb1l[tid];
    for (int idx = tid; idx < 16 * 64; idx += 256) s_nw[idx] = g_nw[i0 * 64 + idx];
    for (int idx = tid; idx < 2048; idx += 256) {
        int row = idx >> 7, col = idx & 127;
        int i = i0 + row, j = jbase + col;
        s_d[idx] = (i == j) ? 0.0f : dist[i * NM1 + j - (j > i ? 1 : 0)];
    }
    __syncthreads();

    int j0 = jbase + warp * 16 + g, j1 = j0 + 8;
    float* st = s_tb + warp * (16 * TSTRIDE);
    float tqgc = (float)tq * GC;

    float acc[8][4];
#pragma unroll
    for (int nt = 0; nt < 8; nt++)
#pragma unroll
        for (int q = 0; q < 4; q++) acc[nt][q] = 0.0f;

#pragma unroll 1
    for (int ii = 0; ii < 16; ii++) {
        int i = i0 + ii;
        float d0 = s_d[ii * 128 + warp * 16 + g];
        float d1 = s_d[ii * 128 + warp * 16 + 8 + g];
        float u0 = fmaf(d0, CSQ, -tqgc);       // d0*c - tq*gc
        float u1 = fmaf(d1, CSQ, -tqgc);

        // ---- GEMM1: u = rbf @ pw1 + pb1 ----
        float u[8][4];
#pragma unroll
        for (int nt = 0; nt < 8; nt++) {
            float2 pb = *(const float2*)&s_pb1[nt * 8 + 2 * tq];
            u[nt][0] = pb.x; u[nt][1] = pb.y; u[nt][2] = pb.x; u[nt][3] = pb.y;
        }
#pragma unroll
        for (int kk = 0; kk < 7; kk++) {
            float t0 = u0 - (float)(kk * 8) * GC;
            float t1 = u1 - (float)(kk * 8) * GC;
            float t2 = u0 - (float)(kk * 8 + 4) * GC;
            float t3 = u1 - (float)(kk * 8 + 4) * GC;
            uint32_t a0 = rbf_bits(t0), a1 = rbf_bits(t1);
            uint32_t a2 = rbf_bits(t2), a3 = rbf_bits(t3);
#pragma unroll
            for (int c4 = 0; c4 < 4; c4++) {
                float4 b = *(const float4*)&s_bf1[kk * 512 + c4 * 128 + lane * 4];
                mma8(u[2 * c4],     a0, a1, a2, a3, __float_as_uint(b.x), __float_as_uint(b.y));
                mma8(u[2 * c4 + 1], a0, a1, a2, a3, __float_as_uint(b.z), __float_as_uint(b.w));
            }
        }

        // ---- softplus, zero diag rows, stage t (raw fp32; MMA truncates) ----
        bool z0 = (j0 == i), z1 = (j1 == i);
        __syncwarp();
#pragma unroll
        for (int nt = 0; nt < 8; nt++) {
            int col = nt * 8 + 2 * tq;
            float2 r0 = make_float2(z0 ? 0.0f : sp_half(u[nt][0]),
                                    z0 ? 0.0f : sp_half(u[nt][1]));
            float2 r1 = make_float2(z1 ? 0.0f : sp_half(u[nt][2]),
                                    z1 ? 0.0f : sp_half(u[nt][3]));
            *(float2*)&st[g * TSTRIDE + col]       = r0;
            *(float2*)&st[(g + 8) * TSTRIDE + col] = r1;
        }
        __syncwarp();

        // ---- GEMM2: u2 = t @ pw2 ----
#pragma unroll
        for (int nt = 0; nt < 8; nt++)
#pragma unroll
            for (int q = 0; q < 4; q++) u[nt][q] = 0.0f;
#pragma unroll
        for (int kk = 0; kk < 8; kk++) {
            int k0 = kk * 8 + tq;
            uint32_t a0 = __float_as_uint(st[g * TSTRIDE + k0]);
            uint32_t a1 = __float_as_uint(st[(g + 8) * TSTRIDE + k0]);
            uint32_t a2 = __float_as_uint(st[g * TSTRIDE + k0 + 4]);
            uint32_t a3 = __float_as_uint(st[(g + 8) * TSTRIDE + k0 + 4]);
#pragma unroll
            for (int c4 = 0; c4 < 4; c4++) {
                float4 b = *(const float4*)&s_bf2[kk * 512 + c4 * 128 + lane * 4];
                mma8(u[2 * c4],     a0, a1, a2, a3, __float_as_uint(b.x), __float_as_uint(b.y));
                mma8(u[2 * c4 + 1], a0, a1, a2, a3, __float_as_uint(b.z), __float_as_uint(b.w));
            }
        }

        // ---- acc += nw[i]_col * u2 ----
#pragma unroll
        for (int nt = 0; nt < 8; nt++) {
            float2 w = *(const float2*)&s_nw[ii * 64 + nt * 8 + 2 * tq];
            acc[nt][0] += w.x * u[nt][0];
            acc[nt][1] += w.y * u[nt][1];
            acc[nt][2] += w.x * u[nt][2];
            acc[nt][3] += w.y * u[nt][3];
        }
    }

#pragma unroll
    for (int nt = 0; nt < 8; nt++) {
        int col = nt * 8 + 2 * tq;
        atomicAdd(&g_agg[j0 * 64 + col],     acc[nt][0]);
        atomicAdd(&g_agg[j0 * 64 + col + 1], acc[nt][1]);
        atomicAdd(&g_agg[j1 * 64 + col],     acc[nt][2]);
        atomicAdd(&g_agg[j1 * 64 + col + 1], acc[nt][3]);
    }
}

// ======================= readout, (i,jt) tiling, inline rbf ==================
__global__ void __launch_bounds__(256, 2)
k_readout(const float* __restrict__ dist,
          const float* __restrict__ ro_w1, const float* __restrict__ ro_b1,
          const float* __restrict__ ro_w2, const float* __restrict__ ro_b2,
          float* __restrict__ out) {
    __shared__ __align__(16) float s_wg[3584];     // rbf-part weights, frag order
    __shared__ __align__(16) float s_wa[64];       // row 0 (ha_src)
    __shared__ __align__(16) float s_wb[64];       // row 1 (ha_dst)
    __shared__ __align__(16) float s_b1[64];
    __shared__ __align__(16) float s_w2[128];      // [64][2]
    __shared__ float s_b2[2];

    int tid  = threadIdx.x;
    int warp = tid >> 5, lane = tid & 31;
    int g = lane >> 2, tq = lane & 3;

    for (int idx = tid; idx < 3584; idx += 256) {
        int kk = idx >> 9, c4 = (idx >> 7) & 3, l = (idx >> 2) & 31, jj = idx & 3;
        int k = kk * 8 + (l & 3) + 4 * (jj & 1);
        int n = (c4 * 2 + (jj >> 1)) * 8 + (l >> 2);
        s_wg[idx] = (k < 50) ? f2tf_f(ro_w1[(2 + k) * 64 + n]) : 0.0f;
    }
    if (tid < 64)  { s_wa[tid] = ro_w1[tid]; s_wb[tid] = ro_w1[64 + tid]; s_b1[tid] = ro_b1[tid]; }
    if (tid < 128) s_w2[tid] = ro_w2[tid];
    if (tid < 2)   s_b2[tid] = ro_b2[tid];
    __syncthreads();

    int t  = blockIdx.x * 8 + warp;                // (i, jt) tile
    int i  = t / NJT, jt = t - i * NJT;
    int j0 = jt * 16 + g, j1 = j0 + 8;
    float hi = g_ha[i], hj0 = g_ha[j0], hj1 = g_ha[j1];
    float d0 = (j0 == i) ? 0.0f : dist[i * NM1 + j0 - (j0 > i ? 1 : 0)];
    float d1 = (j1 == i) ? 0.0f : dist[i * NM1 + j1 - (j1 > i ? 1 : 0)];
    float tqgc = (float)tq * GC;
    float u0 = fmaf(d0, CSQ, -tqgc);
    float u1 = fmaf(d1, CSQ, -tqgc);

    float f[8][4];
#pragma unroll
    for (int nt = 0; nt < 8; nt++) {
        int col = nt * 8 + 2 * tq;
        float2 b  = *(const float2*)&s_b1[col];
        float2 wa = *(const float2*)&s_wa[col];
        float2 wb = *(const float2*)&s_wb[col];
        f[nt][0] = b.x + hi * wa.x + hj0 * wb.x;
        f[nt][1] = b.y + hi * wa.y + hj0 * wb.y;
        f[nt][2] = b.x + hi * wa.x + hj1 * wb.x;
        f[nt][3] = b.y + hi * wa.y + hj1 * wb.y;
    }
#pragma unroll
    for (int kk = 0; kk < 7; kk++) {
        float t0 = u0 - (float)(kk * 8) * GC;
        float t1 = u1 - (float)(kk * 8) * GC;
        float t2 = u0 - (float)(kk * 8 + 4) * GC;
        float t3 = u1 - (float)(kk * 8 + 4) * GC;
        uint32_t a0 = rbf_bits(t0), a1 = rbf_bits(t1);
        uint32_t a2 = rbf_bits(t2), a3 = rbf_bits(t3);
#pragma unroll
        for (int c4 = 0; c4 < 4; c4++) {
            float4 b = *(const float4*)&s_wg[kk * 512 + c4 * 128 + lane * 4];
            mma8(f[2 * c4],     a0, a1, a2, a3, __float_as_uint(b.x), __float_as_uint(b.y));
            mma8(f[2 * c4 + 1], a0, a1, a2, a3, __float_as_uint(b.z), __float_as_uint(b.w));
        }
    }

    // epilogue: relu -> 64x2 head -> 4-lane reduce -> softmax
    float l00 = 0.0f, l01 = 0.0f, l10 = 0.0f, l11 = 0.0f;
#pragma unroll
    for (int nt = 0; nt < 8; nt++) {
        int col = nt * 8 + 2 * tq;
        float4 w = *(const float4*)&s_w2[col * 2];
        float v0 = fmaxf(f[nt][0], 0.0f), v1 = fmaxf(f[nt][1], 0.0f);
        float v2 = fmaxf(f[nt][2], 0.0f), v3 = fmaxf(f[nt][3], 0.0f);
        l00 += v0 * w.x + v1 * w.z;  l01 += v0 * w.y + v1 * w.w;
        l10 += v2 * w.x + v3 * w.z;  l11 += v2 * w.y + v3 * w.w;
    }
#pragma unroll
    for (int off = 1; off <= 2; off <<= 1) {
        l00 += __shfl_xor_sync(0xffffffffu, l00, off);
        l01 += __shfl_xor_sync(0xffffffffu, l01, off);
        l10 += __shfl_xor_sync(0xffffffffu, l10, off);
        l11 += __shfl_xor_sync(0xffffffffu, l11, off);
    }
    if (tq == 0) {
        if (j0 != i) {
            int e0 = i * NM1 + j0 - (j0 > i ? 1 : 0);
            float a = l00 + s_b2[0], b = l01 + s_b2[1];
            float m = fmaxf(a, b);
            float pa = __expf(a - m), pb = __expf(b - m);
            float inv = 1.0f / (pa + pb);
            *(float2*)&out[2 * e0] = make_float2(pa * inv, pb * inv);
        }
        if (j1 != i) {
            int e1 = i * NM1 + j1 - (j1 > i ? 1 : 0);
            float a = l10 + s_b2[0], b = l11 + s_b2[1];
            float m = fmaxf(a, b);
            float pa = __expf(a - m), pb = __expf(b - m);
            float inv = 1.0f / (pa + pb);
            *(float2*)&out[2 * e1] = make_float2(pa * inv, pb * inv);
        }
    }
}

// ---------------- launch ------------------------------------------------------
extern "C" void kernel_launch(void* const* d_in, const int* in_sizes, int n_in,
                              void* d_out, int out_size) {
    const int*   at    = (const int*)  d_in[0];
    const float* dist  = (const float*)d_in[1];
    // d_in[2]=src, d_in[3]=dst implied by complete-graph closed form
    const float* emb   = (const float*)d_in[4];
    const float* w1    = (const float*)d_in[5];
    const float* pw1   = (const float*)d_in[6];
    const float* pb1   = (const float*)d_in[7];
    const float* pw2   = (const float*)d_in[8];
    const float* pb2   = (const float*)d_in[9];
    const float* qw1   = (const float*)d_in[10];
    const float* qb1   = (const float*)d_in[11];
    const float* qw2   = (const float*)d_in[12];
    const float* qb2   = (const float*)d_in[13];
    const float* au_w1 = (const float*)d_in[14];
    const float* au_b1 = (const float*)d_in[15];
    const float* au_w2 = (const float*)d_in[16];
    const float* au_b2 = (const float*)d_in[17];
    const float* ro_w1 = (const float*)d_in[18];
    const float* ro_b1 = (const float*)d_in[19];
    const float* ro_w2 = (const float*)d_in[20];
    const float* ro_b2 = (const float*)d_in[21];
    float* out = (float*)d_out;

    float* nwsum_base;
    cudaGetSymbolAddress((void**)&nwsum_base, g_nwsum);

    const int conv_smem = (3584 + 4096 + 64 + 1024 + 2048 + 8 * 16 * TSTRIDE) * (int)sizeof(float);
    cudaFuncSetAttribute(k_conv, cudaFuncAttributeMaxDynamicSharedMemorySize, conv_smem);

    k_init_h<<<(NA * DIM + 255) / 256, 256>>>(at, emb);
    k_nw<<<NA, DIM>>>(w1, nwsum_base);

    for (int l = 0; l < NCONV; l++) {
        dim3 grid(NA / 128, 48);              // jt-blocks x i-chunks
        k_conv<<<grid, 256, conv_smem>>>(dist, pw1 + l * 50 * DIM, pb1 + l * DIM,
                                         pw2 + l * DIM * DIM);
        int do_nw = (l + 1 < NCONV);
        k_update<<<NA, DIM>>>(qw1 + l * DIM * DIM, qb1 + l * DIM,
                              qw2 + l * DIM * DIM, qb2 + l * DIM,
                              pb2 + l * DIM, nwsum_base + l * DIM,
                              do_nw ? (w1 + (l + 1) * DIM * DIM) : w1,
                              do_nw ? (nwsum_base + (l + 1) * DIM) : nwsum_base,
                              do_nw);
    }
    k_atom<<<NA, DIM>>>(au_w1, au_b1, au_w2, au_b2);
    k_readout<<<NA * NJT / 8, 256>>>(dist, ro_w1, ro_b1, ro_w2, ro_b2, out);
}